// round 8
// baseline (speedup 1.0000x reference)
#include <cuda_runtime.h>
#include <cstdint>
#include <math.h>

// ---------------- problem constants ----------------
#define T_STEPS 512
#define BATCH   64
#define EMB_D   400
#define HID_D   1152
#define M_ROWS  (T_STEPS * BATCH)   // 32768

// ---------------- scratch (static device memory; no cudaMalloc allowed) ----
__device__ float g_act0[(size_t)M_ROWS * HID_D];        // 151 MB
__device__ float g_act1[(size_t)M_ROWS * HID_D];        // 151 MB
__device__ float g_xw[(size_t)M_ROWS * 4 * HID_D];      // 604 MB
__device__ float g_h[2][BATCH * HID_D];                 // k-major hidden: [H][64], 2 bufs
__device__ unsigned int g_arrive;                       // grid barrier counter

// ---------------- packed f32x2 helpers ----------------
__device__ __forceinline__ unsigned long long pack2(float lo, float hi) {
    unsigned long long r;
    asm("mov.b64 %0, {%1, %2};" : "=l"(r) : "f"(lo), "f"(hi));
    return r;
}
__device__ __forceinline__ void unpack2(unsigned long long v, float& lo, float& hi) {
    asm("mov.b64 {%0, %1}, %2;" : "=f"(lo), "=f"(hi) : "l"(v));
}
__device__ __forceinline__ unsigned long long fma2(unsigned long long a,
                                                   unsigned long long b,
                                                   unsigned long long c) {
    unsigned long long d;
    asm("fma.rn.f32x2 %0, %1, %2, %3;" : "=l"(d) : "l"(a), "l"(b), "l"(c));
    return d;
}

__device__ __forceinline__ void cpasync16(uint32_t saddr, const float* g) {
    asm volatile("cp.async.cg.shared.global [%0], [%1], 16;" :: "r"(saddr), "l"(g));
}
__device__ __forceinline__ void cpcommit() {
    asm volatile("cp.async.commit_group;" ::: "memory");
}

// ---------------- helpers ----------------
__device__ __forceinline__ float sigm(float x) { return 1.0f / (1.0f + expf(-x)); }

__device__ __forceinline__ void grid_barrier(int nctas, unsigned int target) {
    __syncthreads();
    if (threadIdx.x == 0) {
        __threadfence();
        atomicAdd(&g_arrive, 1u);
        unsigned int v;
        do {
            asm volatile("ld.acquire.gpu.u32 %0, [%1];" : "=r"(v) : "l"(&g_arrive) : "memory");
        } while (v < target);
    }
    __syncthreads();
}

__global__ void reset_bar_kernel() { g_arrive = 0u; }

// ---------------- embedding gather ----------------
__global__ void embed_kernel(const int* __restrict__ x, const float* __restrict__ emb,
                             float* __restrict__ out) {
    const int m = blockIdx.x;
    const int tok = x[m];
    const float4* src = (const float4*)(emb + (size_t)tok * EMB_D);
    float4* dst = (float4*)(out + (size_t)m * EMB_D);
    for (int i = threadIdx.x; i < EMB_D / 4; i += blockDim.x) dst[i] = src[i];
}

// ---------------- input projection v2 (unchanged from round 7) ----------------
__global__ void __launch_bounds__(256, 1)
gemm_xw2_kernel(const float* __restrict__ A, const float* __restrict__ W,
                const float* __restrict__ bih, const float* __restrict__ bhh,
                float* __restrict__ out, int N, int K) {
    extern __shared__ float smg[];
    float* sAs = smg;                    // [2][16][256]
    float* sBs = smg + 2 * 16 * 256;     // [2][16][128]

    const int tid = threadIdx.x;
    const int tm  = tid & 15;
    const int tn  = tid >> 4;
    const int m0  = blockIdx.y * 256;
    const int n0  = blockIdx.x * 128;

    const float* Ap = A + (size_t)(m0 + tid) * K;
    const int fst  = tid ^ ((tid >> 1) & 0x1C);
    const int bn   = tid >> 1;
    const int bkq  = (tid & 1) * 8;
    const float* Wp = W + (size_t)(n0 + bn) * K + bkq;
    const bool bok  = (n0 + bn) < N;

    int aoff[4];
#pragma unroll
    for (int j = 0; j < 4; ++j) {
        const int m = tm * 16 + j * 4;
        aoff[j] = m ^ ((m >> 1) & 0x1C);
    }

    const int NT = K / 16;

    unsigned long long acc[16][4];
#pragma unroll
    for (int i = 0; i < 16; ++i)
#pragma unroll
        for (int jp = 0; jp < 4; ++jp) acc[i][jp] = 0ull;

    const float4 z4 = make_float4(0.f, 0.f, 0.f, 0.f);
    float4 apf[4], bpf[2];

#pragma unroll
    for (int j = 0; j < 4; ++j) apf[j] = *(const float4*)(Ap + j * 4);
    bpf[0] = bok ? *(const float4*)(Wp)     : z4;
    bpf[1] = bok ? *(const float4*)(Wp + 4) : z4;
    {
        float* sa = sAs;
        float* sb = sBs;
#pragma unroll
        for (int j = 0; j < 4; ++j) {
            sa[(j * 4 + 0) * 256 + fst] = apf[j].x;
            sa[(j * 4 + 1) * 256 + fst] = apf[j].y;
            sa[(j * 4 + 2) * 256 + fst] = apf[j].z;
            sa[(j * 4 + 3) * 256 + fst] = apf[j].w;
        }
        sb[(bkq + 0) * 128 + bn] = bpf[0].x;
        sb[(bkq + 1) * 128 + bn] = bpf[0].y;
        sb[(bkq + 2) * 128 + bn] = bpf[0].z;
        sb[(bkq + 3) * 128 + bn] = bpf[0].w;
        sb[(bkq + 4) * 128 + bn] = bpf[1].x;
        sb[(bkq + 5) * 128 + bn] = bpf[1].y;
        sb[(bkq + 6) * 128 + bn] = bpf[1].z;
        sb[(bkq + 7) * 128 + bn] = bpf[1].w;
    }
    __syncthreads();

    for (int it = 0; it < NT; ++it) {
        const int nxt = it + 1;
        if (nxt < NT) {
            const float* ap2 = Ap + nxt * 16;
#pragma unroll
            for (int j = 0; j < 4; ++j) apf[j] = *(const float4*)(ap2 + j * 4);
            const float* wp2 = Wp + nxt * 16;
            bpf[0] = bok ? *(const float4*)(wp2)     : z4;
            bpf[1] = bok ? *(const float4*)(wp2 + 4) : z4;
        }
        {
            const float* sa = sAs + (it & 1) * (16 * 256);
            const float* sb = sBs + (it & 1) * (16 * 128);
#pragma unroll
            for (int k = 0; k < 16; ++k) {
                float ra[16];
                *(float4*)&ra[0]  = *(const float4*)(sa + k * 256 + aoff[0]);
                *(float4*)&ra[4]  = *(const float4*)(sa + k * 256 + aoff[1]);
                *(float4*)&ra[8]  = *(const float4*)(sa + k * 256 + aoff[2]);
                *(float4*)&ra[12] = *(const float4*)(sa + k * 256 + aoff[3]);
                const ulonglong2 b01 = *(const ulonglong2*)(sb + k * 128 + tn * 8);
                const ulonglong2 b23 = *(const ulonglong2*)(sb + k * 128 + tn * 8 + 4);
                unsigned long long rb[4] = {b01.x, b01.y, b23.x, b23.y};
#pragma unroll
                for (int i = 0; i < 16; ++i) {
                    const unsigned long long ai = pack2(ra[i], ra[i]);
#pragma unroll
                    for (int jp = 0; jp < 4; ++jp)
                        acc[i][jp] = fma2(ai, rb[jp], acc[i][jp]);
                }
            }
        }
        if (nxt < NT) {
            float* sa = sAs + (nxt & 1) * (16 * 256);
            float* sb = sBs + (nxt & 1) * (16 * 128);
#pragma unroll
            for (int j = 0; j < 4; ++j) {
                sa[(j * 4 + 0) * 256 + fst] = apf[j].x;
                sa[(j * 4 + 1) * 256 + fst] = apf[j].y;
                sa[(j * 4 + 2) * 256 + fst] = apf[j].z;
                sa[(j * 4 + 3) * 256 + fst] = apf[j].w;
            }
            sb[(bkq + 0) * 128 + bn] = bpf[0].x;
            sb[(bkq + 1) * 128 + bn] = bpf[0].y;
            sb[(bkq + 2) * 128 + bn] = bpf[0].z;
            sb[(bkq + 3) * 128 + bn] = bpf[0].w;
            sb[(bkq + 4) * 128 + bn] = bpf[1].x;
            sb[(bkq + 5) * 128 + bn] = bpf[1].y;
            sb[(bkq + 6) * 128 + bn] = bpf[1].z;
            sb[(bkq + 7) * 128 + bn] = bpf[1].w;
        }
        __syncthreads();
    }

    float bias[8];
#pragma unroll
    for (int jj = 0; jj < 8; ++jj) {
        const int n = n0 + tn * 8 + jj;
        bias[jj] = (n < N) ? (__ldg(bih + n) + __ldg(bhh + n)) : 0.0f;
    }
    const bool full = (n0 + 128 <= N);
#pragma unroll
    for (int i = 0; i < 16; ++i) {
        float vals[8];
#pragma unroll
        for (int jp = 0; jp < 4; ++jp) unpack2(acc[i][jp], vals[2 * jp], vals[2 * jp + 1]);
#pragma unroll
        for (int jj = 0; jj < 8; ++jj) vals[jj] += bias[jj];
        float* orow = out + (size_t)(m0 + tm * 16 + i) * N + n0 + tn * 8;
        if (full) {
            *(float4*)orow       = make_float4(vals[0], vals[1], vals[2], vals[3]);
            *(float4*)(orow + 4) = make_float4(vals[4], vals[5], vals[6], vals[7]);
        } else {
#pragma unroll
            for (int jj = 0; jj < 8; ++jj)
                if (n0 + tn * 8 + jj < N) orow[jj] = vals[jj];
        }
    }
}

// ---------------- persistent recurrent LSTM layer (v5) ----------------
// 384 threads = 12 warps = 12 k-slices (3 warps/SMSP for latency hiding).
// Each warp: all 32 gate rows x 64 batches over its KSL-k slice.
// Chunks of 8 k, double-buffered cp.async staging.
// 12 partials reduced in two rounds through 6 SMEM slots (aliased on stage).
// KSL*12 may exceed H (layer 2): W zero-padded, h over-reads hit zero weights.
template <int H, int KSL>
__global__ void __launch_bounds__(384, 1)
lstm_rec5_kernel(const float* __restrict__ xw, const float* __restrict__ Whh,
                 float* __restrict__ out, int nctas) {
    constexpr int KPADZ = ((KSL + 7) / 8) * 8;   // 96 / 40
    constexpr int NCH   = KPADZ / 8;             // 12 / 5
    constexpr int WFL   = 12 * KPADZ * 32;

    extern __shared__ float sm[];
    float* sW     = sm;                          // [12 z][KPADZ][32 rows]
    float* sStage = sW + WFL;                    // [2 buf][12 z][8 k][64 b] = 12288 fl
    float* sC     = sStage;                      // alias: [6 slot][64 b][32 r] = 12288 fl
    float* sCell  = sStage + 12288;              // [512]

    const int tid  = threadIdx.x;
    const int z    = tid >> 5;                   // warp = k-slice (0..11)
    const int lane = tid & 31;
    const int rgrp = lane & 3;                   // rows rgrp*8..+7
    const int bg   = lane >> 2;                  // batches bg*8..+7
    const int j0   = blockIdx.x * 8;

    // ---- init: W_hh -> SMEM, zero-padded ----
    for (int idx = tid; idx < WFL; idx += 384) {
        const int r  = idx & 31;
        const int kl = idx >> 5;
        const int zz = kl / KPADZ;
        const int kp = kl - zz * KPADZ;
        const int kglob = zz * KSL + kp;
        float v = 0.0f;
        if (kp < KSL && kglob < H) {
            const int grow = (r >> 3) * H + j0 + (r & 7);
            v = Whh[(size_t)grow * H + kglob];
        }
        sW[idx] = v;
    }
    // zero cell + this CTA's rows of h buffer 0
    for (int i = tid; i < 512; i += 384) {
        sCell[i] = 0.0f;
        const int u = i & 7, b = i >> 3;
        g_h[0][(j0 + u) * 64 + b] = 0.0f;
    }
    unsigned int ep = 1;
    grid_barrier(nctas, ep * (unsigned)nctas); ++ep;

    // gate-phase cells: c0 = tid (all), c1 = tid + 384 (tid < 128)
    const int c0b = tid >> 3, c0u = tid & 7;
    const int c1b = (tid + 384) >> 3, c1u = tid & 7;
    const bool has_c1 = (tid < 128);

    const uint32_t stage_s = (uint32_t)__cvta_generic_to_shared(sStage);
    const float* wbase = sW + z * KPADZ * 32;

    for (int t = 0; t < T_STEPS; ++t) {
        const float* hbuf = g_h[t & 1];
        float* hnext = g_h[1 - (t & 1)];

        // prefetch xw
        float xwv[2][4];
        {
            const float* xb0 = xw + ((size_t)t * 64 + c0b) * (4 * H) + j0 + c0u;
#pragma unroll
            for (int g = 0; g < 4; ++g) xwv[0][g] = __ldg(xb0 + g * H);
            if (has_c1) {
                const float* xb1 = xw + ((size_t)t * 64 + c1b) * (4 * H) + j0 + c1u;
#pragma unroll
                for (int g = 0; g < 4; ++g) xwv[1][g] = __ldg(xb1 + g * H);
            }
        }

        // stage chunk 0: 1536 float4 over 384 threads (4 each)
        // slice-chunk = 128 consecutive float4 in k-major g_h
#pragma unroll
        for (int j = 0; j < 4; ++j) {
            const int idx = j * 384 + tid;
            const int z2 = idx >> 7, f = idx & 127;
            cpasync16(stage_s + (uint32_t)(z2 * 512 + f * 4) * 4,
                      hbuf + (z2 * KSL) * 64 + f * 4);
        }
        cpcommit();

        unsigned long long acc[4][8];
#pragma unroll
        for (int rp = 0; rp < 4; ++rp)
#pragma unroll
            for (int b = 0; b < 8; ++b) acc[rp][b] = 0ull;

        for (int ci = 0; ci < NCH; ++ci) {
            if (ci + 1 < NCH) {
                const int buf = (ci + 1) & 1;
#pragma unroll
                for (int j = 0; j < 4; ++j) {
                    const int idx = j * 384 + tid;
                    const int z2 = idx >> 7, f = idx & 127;
                    cpasync16(stage_s + (uint32_t)(buf * 6144 + z2 * 512 + f * 4) * 4,
                              hbuf + (z2 * KSL + (ci + 1) * 8) * 64 + f * 4);
                }
                cpcommit();
                asm volatile("cp.async.wait_group 1;" ::: "memory");
            } else {
                asm volatile("cp.async.wait_group 0;" ::: "memory");
            }
            __syncthreads();

            const float4* a4 = (const float4*)sStage + (ci & 1) * 1536 + z * 128;
            const ulonglong2* w2 = (const ulonglong2*)(wbase + ci * 8 * 32) + rgrp * 2;
#pragma unroll
            for (int kk = 0; kk < 8; ++kk) {
                const float4 h01 = a4[kk * 16 + bg * 2];
                const float4 h23 = a4[kk * 16 + bg * 2 + 1];
                const ulonglong2 wA = w2[kk * 8];
                const ulonglong2 wB = w2[kk * 8 + 1];
                const unsigned long long hp0 = pack2(h01.x, h01.x);
                const unsigned long long hp1 = pack2(h01.y, h01.y);
                const unsigned long long hp2 = pack2(h01.z, h01.z);
                const unsigned long long hp3 = pack2(h01.w, h01.w);
                const unsigned long long hp4 = pack2(h23.x, h23.x);
                const unsigned long long hp5 = pack2(h23.y, h23.y);
                const unsigned long long hp6 = pack2(h23.z, h23.z);
                const unsigned long long hp7 = pack2(h23.w, h23.w);
                acc[0][0] = fma2(wA.x, hp0, acc[0][0]);
                acc[1][0] = fma2(wA.y, hp0, acc[1][0]);
                acc[2][0] = fma2(wB.x, hp0, acc[2][0]);
                acc[3][0] = fma2(wB.y, hp0, acc[3][0]);
                acc[0][1] = fma2(wA.x, hp1, acc[0][1]);
                acc[1][1] = fma2(wA.y, hp1, acc[1][1]);
                acc[2][1] = fma2(wB.x, hp1, acc[2][1]);
                acc[3][1] = fma2(wB.y, hp1, acc[3][1]);
                acc[0][2] = fma2(wA.x, hp2, acc[0][2]);
                acc[1][2] = fma2(wA.y, hp2, acc[1][2]);
                acc[2][2] = fma2(wB.x, hp2, acc[2][2]);
                acc[3][2] = fma2(wB.y, hp2, acc[3][2]);
                acc[0][3] = fma2(wA.x, hp3, acc[0][3]);
                acc[1][3] = fma2(wA.y, hp3, acc[1][3]);
                acc[2][3] = fma2(wB.x, hp3, acc[2][3]);
                acc[3][3] = fma2(wB.y, hp3, acc[3][3]);
                acc[0][4] = fma2(wA.x, hp4, acc[0][4]);
                acc[1][4] = fma2(wA.y, hp4, acc[1][4]);
                acc[2][4] = fma2(wB.x, hp4, acc[2][4]);
                acc[3][4] = fma2(wB.y, hp4, acc[3][4]);
                acc[0][5] = fma2(wA.x, hp5, acc[0][5]);
                acc[1][5] = fma2(wA.y, hp5, acc[1][5]);
                acc[2][5] = fma2(wB.x, hp5, acc[2][5]);
                acc[3][5] = fma2(wB.y, hp5, acc[3][5]);
                acc[0][6] = fma2(wA.x, hp6, acc[0][6]);
                acc[1][6] = fma2(wA.y, hp6, acc[1][6]);
                acc[2][6] = fma2(wB.x, hp6, acc[2][6]);
                acc[3][6] = fma2(wB.y, hp6, acc[3][6]);
                acc[0][7] = fma2(wA.x, hp7, acc[0][7]);
                acc[1][7] = fma2(wA.y, hp7, acc[1][7]);
                acc[2][7] = fma2(wB.x, hp7, acc[2][7]);
                acc[3][7] = fma2(wB.y, hp7, acc[3][7]);
            }
        }
        __syncthreads();   // all reads of stage done before aliasing as sC

        // ---- round 1: warps 6..11 write partials into slots 0..5 ----
        if (z >= 6) {
#pragma unroll
            for (int b = 0; b < 8; ++b) {
                float* p = sC + (z - 6) * 2048 + (bg * 8 + b) * 32 + rgrp * 8;
                *(ulonglong2*)p       = make_ulonglong2(acc[0][b], acc[1][b]);
                *(ulonglong2*)(p + 4) = make_ulonglong2(acc[2][b], acc[3][b]);
            }
        }
        __syncthreads();
        // ---- round 2: warps 0..5 add their partials in place ----
        if (z < 6) {
#pragma unroll
            for (int b = 0; b < 8; ++b) {
                float* p = sC + z * 2048 + (bg * 8 + b) * 32 + rgrp * 8;
                ulonglong2 q0 = *(const ulonglong2*)p;
                ulonglong2 q1 = *(const ulonglong2*)(p + 4);
                q0.x = fma2(acc[0][b], pack2(1.f, 1.f), q0.x);
                q0.y = fma2(acc[1][b], pack2(1.f, 1.f), q0.y);
                q1.x = fma2(acc[2][b], pack2(1.f, 1.f), q1.x);
                q1.y = fma2(acc[3][b], pack2(1.f, 1.f), q1.y);
                *(ulonglong2*)p       = q0;
                *(ulonglong2*)(p + 4) = q1;
            }
        }
        __syncthreads();

        // ---- final reduce over 6 slots + gates ----
#pragma unroll
        for (int cc = 0; cc < 2; ++cc) {
            if (cc == 1 && !has_c1) break;
            const int b = cc ? c1b : c0b;
            const int u = cc ? c1u : c0u;
            float gsum[4];
#pragma unroll
            for (int g = 0; g < 4; ++g) {
                const int o = b * 32 + g * 8 + u;
                float s = sC[o] + sC[2048 + o];
                s += sC[2 * 2048 + o] + sC[3 * 2048 + o];
                s += sC[4 * 2048 + o] + sC[5 * 2048 + o];
                gsum[g] = s + xwv[cc][g];
            }
            const int cell = b * 8 + u;
            float c = sCell[cell];
            c = sigm(gsum[1]) * c + sigm(gsum[0]) * tanhf(gsum[2]);
            sCell[cell] = c;
            const float hv = sigm(gsum[3]) * tanhf(c);
            hnext[(j0 + u) * 64 + b] = hv;
            out[((size_t)t * 64 + b) * H + j0 + u] = hv;
        }
        grid_barrier(nctas, ep * (unsigned)nctas); ++ep;
    }
}

// ---------------- launch ----------------
extern "C" void kernel_launch(void* const* d_in, const int* in_sizes, int n_in,
                              void* d_out, int out_size) {
    (void)in_sizes; (void)n_in; (void)out_size;
    const int*   x    = (const int*)d_in[0];
    const float* emb  = (const float*)d_in[1];
    const float* Wih0 = (const float*)d_in[2];
    const float* Whh0 = (const float*)d_in[3];
    const float* bih0 = (const float*)d_in[4];
    const float* bhh0 = (const float*)d_in[5];
    const float* Wih1 = (const float*)d_in[6];
    const float* Whh1 = (const float*)d_in[7];
    const float* bih1 = (const float*)d_in[8];
    const float* bhh1 = (const float*)d_in[9];
    const float* Wih2 = (const float*)d_in[10];
    const float* Whh2 = (const float*)d_in[11];
    const float* bih2 = (const float*)d_in[12];
    const float* bhh2 = (const float*)d_in[13];
    float* out = (float*)d_out;

    float *act0, *act1, *xw;
    cudaGetSymbolAddress((void**)&act0, g_act0);
    cudaGetSymbolAddress((void**)&act1, g_act1);
    cudaGetSymbolAddress((void**)&xw, g_xw);

    const size_t SMEM_GEMM  = (size_t)(2 * 16 * 256 + 2 * 16 * 128) * sizeof(float); // 49152
    const size_t SMEM_BIG   = (size_t)(12 * 96 * 32 + 12288 + 512) * sizeof(float);  // 198656
    const size_t SMEM_SMALL = (size_t)(12 * 40 * 32 + 12288 + 512) * sizeof(float);  // 112640
    cudaFuncSetAttribute((const void*)gemm_xw2_kernel,
                         cudaFuncAttributeMaxDynamicSharedMemorySize, (int)SMEM_GEMM);
    cudaFuncSetAttribute((const void*)lstm_rec5_kernel<HID_D, 96>,
                         cudaFuncAttributeMaxDynamicSharedMemorySize, (int)SMEM_BIG);
    cudaFuncSetAttribute((const void*)lstm_rec5_kernel<EMB_D, 34>,
                         cudaFuncAttributeMaxDynamicSharedMemorySize, (int)SMEM_SMALL);

    // embedding
    embed_kernel<<<M_ROWS, 128>>>(x, emb, act0);

    // layer 0: din=400, H=1152
    gemm_xw2_kernel<<<dim3(36, 128), 256, SMEM_GEMM>>>(act0, Wih0, bih0, bhh0, xw, 4 * HID_D, EMB_D);
    reset_bar_kernel<<<1, 1>>>();
    lstm_rec5_kernel<HID_D, 96><<<144, 384, SMEM_BIG>>>(xw, Whh0, act1, 144);

    // layer 1: din=1152, H=1152
    gemm_xw2_kernel<<<dim3(36, 128), 256, SMEM_GEMM>>>(act1, Wih1, bih1, bhh1, xw, 4 * HID_D, HID_D);
    reset_bar_kernel<<<1, 1>>>();
    lstm_rec5_kernel<HID_D, 96><<<144, 384, SMEM_BIG>>>(xw, Whh1, act0, 144);

    // layer 2: din=1152, H=400 (12 slices of 34, zero-padded)
    gemm_xw2_kernel<<<dim3(13, 128), 256, SMEM_GEMM>>>(act0, Wih2, bih2, bhh2, xw, 4 * EMB_D, HID_D);
    reset_bar_kernel<<<1, 1>>>();
    lstm_rec5_kernel<EMB_D, 34><<<50, 384, SMEM_SMALL>>>(xw, Whh2, out, 50);
}